// round 16
// baseline (speedup 1.0000x reference)
#include <cuda_runtime.h>
#include <cstdint>
#include <math.h>

#define MAXN 100000
#define MAXE 1600000
#define D 64
#define EPSF 1e-12f
#define SEPS 1e-6f
#define TAUF 0.5f

#define EBLOCKS 592          // 4 blocks/SM x 148 SMs
#define ETHREADS 256
#define NT (EBLOCKS * ETHREADS)
#define MAXK 12

// ---- scratch (device globals: no allocation allowed) ----
__device__ __align__(8)  float2 g_deghist[MAXN];   // {weighted deg, edge count}
__device__ float    g_rho[MAXN];
__device__ int      g_start[MAXN];
__device__ int      g_cursor[MAXN];
__device__ __align__(16) float4 g_pay[MAXE];  // {bitcast col, wh, kappa, bitcast eid}
__device__ __align__(16) float g_agg[MAXN * D];
__device__ unsigned g_maxbits;
__device__ int      g_base;
__device__ int      g_is64;
__device__ int      g_bar1, g_bar2;

__device__ __forceinline__ int get_idx(const void* ei, long long pos) {
    if (g_is64) return (int)((const long long*)ei)[pos];
    return ((const int*)ei)[pos];
}

// ---- 0: zero node scratch + barrier counters + dtype detect (block 0) ----
__global__ void k_init(const int* __restrict__ eib, int n_nodes) {
    if (blockIdx.x == 0) {
        __shared__ int any;
        if (threadIdx.x == 0) any = 0;
        __syncthreads();
        int acc = 0;
        for (int j = threadIdx.x; j < 2048; j += blockDim.x)
            acc |= eib[2 * j + 1];
        if (acc != 0) atomicOr(&any, 1);
        __syncthreads();
        if (threadIdx.x == 0) {
            g_is64 = (any == 0) ? 1 : 0;
            g_maxbits = 0u;
            g_base = 0;
            g_bar1 = 0;
            g_bar2 = 0;
        }
    }
    int i = blockIdx.x * blockDim.x + threadIdx.x;
    if (i < n_nodes)
        g_deghist[i] = make_float2(0.f, 0.f);
}

// software grid barrier: all EBLOCKS blocks are co-resident by construction
__device__ __forceinline__ void grid_barrier(int* bar) {
    __syncthreads();
    if (threadIdx.x == 0) {
        __threadfence();
        atomicAdd(bar, 1);
        while (atomicAdd(bar, 0) < EBLOCKS) { }
    }
    __syncthreads();
}

// ---- 1: persistent fused edge pipeline ----
__global__ void __launch_bounds__(ETHREADS, 4)
k_edge(const void* __restrict__ ei, const float* __restrict__ w,
       float* __restrict__ out_ei, int n_edges, int n_nodes) {
    int gtid = blockIdx.x * ETHREADS + threadIdx.x;

    int er[MAXK], ec[MAXK];
    float kap[MAXK];

    // ---- phase A: convert + out_ei + {deg,count} reduction ----
    #pragma unroll
    for (int k = 0; k < MAXK; k++) {
        int e = gtid + k * NT;
        er[k] = -1;
        if (e < n_edges) {
            int r = get_idx(ei, e);
            int c = get_idx(ei, (long long)n_edges + e);
            er[k] = r; ec[k] = c;
            if (out_ei) {
                out_ei[e] = (float)r;
                out_ei[n_edges + e] = (float)c;
            }
            float* dst = (float*)&g_deghist[r];
            asm volatile("red.global.add.v2.f32 [%0], {%1,%2};"
                         :: "l"(dst), "f"(w[e]), "f"(1.0f) : "memory");
        }
    }

    grid_barrier(&g_bar1);

    // ---- phase B: kappa + max|kappa| + CSR-start rider ----
    float m = 0.f;
    #pragma unroll
    for (int k = 0; k < MAXK; k++) {
        if (er[k] >= 0) {
            float idu = 2.f / fmaxf(g_deghist[er[k]].x, EPSF);
            float idv = 2.f / fmaxf(g_deghist[ec[k]].x, EPSF);
            kap[k] = idu + idv - 2.f;
            m = fmaxf(m, fabsf(kap[k]));
        }
    }
    #pragma unroll
    for (int o = 16; o > 0; o >>= 1)
        m = fmaxf(m, __shfl_xor_sync(0xffffffffu, m, o));
    if ((threadIdx.x & 31) == 0)
        atomicMax(&g_maxbits, __float_as_uint(m));

    {
        __shared__ int sh[ETHREADS];
        __shared__ int sbase;
        int t = threadIdx.x;
        if (blockIdx.x * ETHREADS < (unsigned)n_nodes) {
            int n = blockIdx.x * ETHREADS + t;
            int v = (n < n_nodes) ? (int)g_deghist[n].y : 0;
            sh[t] = v;
            __syncthreads();
            #pragma unroll
            for (int o = 1; o < ETHREADS; o <<= 1) {
                int u = (t >= o) ? sh[t - o] : 0;
                __syncthreads();
                sh[t] += u;
                __syncthreads();
            }
            int incl = sh[t];
            if (t == ETHREADS - 1) sbase = atomicAdd(&g_base, incl);
            __syncthreads();
            if (n < n_nodes) {
                int s = sbase + incl - v;
                g_start[n] = s;
                g_cursor[n] = s;
            }
        }
    }

    grid_barrier(&g_bar2);

    // ---- phase C: whalf + surgery + payload scatter ----
    float dt = 0.5f / (__uint_as_float(g_maxbits) + 1e-6f);
    #pragma unroll
    for (int k = 0; k < MAXK; k++) {
        int e = gtid + k * NT;
        if (er[k] >= 0) {
            float wh = fmaxf(w[e] * (1.f - 0.5f * dt * kap[k]), 0.f);
            if (wh <= SEPS) wh = 0.f;
            int pos = atomicAdd(&g_cursor[er[k]], 1);
            g_pay[pos] = make_float4(__int_as_float(ec[k]), wh, kap[k],
                                     __int_as_float(e));
        }
    }
}

// ---- 2: single-pass gather: stats + accumulate + rho + out_wn ----
__global__ void k_gather(const float* __restrict__ x,
                         float* __restrict__ out_wn, int n_nodes) {
    int node = (blockIdx.x * blockDim.x + threadIdx.x) >> 5;
    if (node >= n_nodes) return;
    int lane = threadIdx.x & 31;
    int sub  = lane & 15;
    int half = lane >> 4;
    int s = g_start[node];
    int deg = (int)g_deghist[node].y;

    float rs = 0.f, cn = 0.f, ks = 0.f;
    float4 acc = make_float4(0.f, 0.f, 0.f, 0.f);
    #pragma unroll 2
    for (int j = half; j < deg; j += 2) {
        float4 pl = g_pay[s + j];
        float wh = pl.y;
        rs += wh;
        if (wh != 0.f) {
            cn += 1.f;
            ks += pl.z;
            int c = __float_as_int(pl.x);
            float4 v = ((const float4*)(x + (size_t)c * D))[sub];
            acc.x += wh * v.x; acc.y += wh * v.y;
            acc.z += wh * v.z; acc.w += wh * v.w;
        }
    }
    rs += __shfl_xor_sync(0xffffffffu, rs, 16);
    cn += __shfl_xor_sync(0xffffffffu, cn, 16);
    ks += __shfl_xor_sync(0xffffffffu, ks, 16);
    acc.x += __shfl_xor_sync(0xffffffffu, acc.x, 16);
    acc.y += __shfl_xor_sync(0xffffffffu, acc.y, 16);
    acc.z += __shfl_xor_sync(0xffffffffu, acc.z, 16);
    acc.w += __shfl_xor_sync(0xffffffffu, acc.w, 16);

    float irs = 1.f / fmaxf(rs, EPSF);
    if (lane == 0) {
        float mk = ks / fmaxf(cn, 1.f);
        g_rho[node] = 1.f / (1.f + expf(-mk));
    }
    if (half == 0) {
        acc.x *= irs; acc.y *= irs; acc.z *= irs; acc.w *= irs;
        *(float4*)(g_agg + (size_t)node * D + sub * 4) = acc;
    }

    if (out_wn) {
        for (int j = lane; j < deg; j += 32) {
            float4 pl = g_pay[s + j];
            out_wn[__float_as_int(pl.w)] = pl.y * irs;
        }
    }
}

// ---- FFMA2 helpers (packed f32x2, sm_103a) ----
__device__ __forceinline__ unsigned long long dup2(float v) {
    unsigned long long r;
    asm("mov.b64 %0, {%1, %1};" : "=l"(r) : "r"(__float_as_uint(v)));
    return r;
}
__device__ __forceinline__ void ffma2(unsigned long long& acc,
                                      unsigned long long a, unsigned long long b) {
    asm("fma.rn.f32x2 %0, %1, %2, %0;" : "+l"(acc) : "l"(a), "l"(b));
}
__device__ __forceinline__ void unpack2(unsigned long long v, float& lo, float& hi) {
    unsigned l, h;
    asm("mov.b64 {%0, %1}, %2;" : "=r"(l), "=r"(h) : "l"(v));
    lo = __uint_as_float(l); hi = __uint_as_float(h);
}

// ---- 3: two-pass fused GEMM (FFMA2, 48KB smem, 4 blocks/SM) ----
// out = (rho*x)@Ws^T + agg@Wn^T + tau*x
#define TILE_N 128
__global__ __launch_bounds__(256, 4) void k_gemm(const float* __restrict__ x,
                                                 const float* __restrict__ Ws,
                                                 const float* __restrict__ Wn,
                                                 float* __restrict__ out,
                                                 int n_nodes) {
    __shared__ float buf[D * TILE_N];   // 32KB: operand tile, transposed [k][n]
    __shared__ float wT[D * D];         // 16KB: weight tile, transposed [k][d]

    int t = threadIdx.x;
    int nbase = blockIdx.x * TILE_N;
    int ng = t >> 3;   // 0..31 -> nodes ng*4 .. +3
    int dg = t & 7;    // 0..7  -> dims  dg*8 .. +7 (4 packed pairs)

    unsigned long long acc[4][4];
    #pragma unroll
    for (int i = 0; i < 4; i++)
        #pragma unroll
        for (int j = 0; j < 4; j++) acc[i][j] = 0ull;

    #pragma unroll
    for (int pass = 0; pass < 2; pass++) {
        const float* W = (pass == 0) ? Ws : Wn;
        // stage weights transposed
        for (int i = t; i < D * D; i += 256) {
            int k = i >> 6, d = i & 63;
            wT[k * D + d] = W[d * D + k];
        }
        // stage operand transposed: pass0 = rho*x, pass1 = agg
        for (int i = t; i < TILE_N * (D / 4); i += 256) {
            int n  = i & (TILE_N - 1);
            int k4 = i >> 7;
            int gn = nbase + n;
            float4 v = make_float4(0.f, 0.f, 0.f, 0.f);
            if (gn < n_nodes) {
                if (pass == 0) {
                    v = *(const float4*)(x + (size_t)gn * D + k4 * 4);
                    float rho = g_rho[gn];
                    v.x *= rho; v.y *= rho; v.z *= rho; v.w *= rho;
                } else {
                    v = *(const float4*)(g_agg + (size_t)gn * D + k4 * 4);
                }
            }
            buf[(k4 * 4 + 0) * TILE_N + n] = v.x;
            buf[(k4 * 4 + 1) * TILE_N + n] = v.y;
            buf[(k4 * 4 + 2) * TILE_N + n] = v.z;
            buf[(k4 * 4 + 3) * TILE_N + n] = v.w;
        }
        __syncthreads();

        #pragma unroll 4
        for (int k = 0; k < D; k++) {
            float4 a = *(float4*)&buf[k * TILE_N + ng * 4];
            ulonglong2 b0 = *(ulonglong2*)&wT[k * D + dg * 8];
            ulonglong2 b1 = *(ulonglong2*)&wT[k * D + dg * 8 + 4];
            unsigned long long bv[4] = {b0.x, b0.y, b1.x, b1.y};
            float av[4] = {a.x, a.y, a.z, a.w};
            #pragma unroll
            for (int i = 0; i < 4; i++) {
                unsigned long long ad = dup2(av[i]);
                #pragma unroll
                for (int j = 0; j < 4; j++)
                    ffma2(acc[i][j], ad, bv[j]);
            }
        }
        __syncthreads();   // safe to restage buf/wT
    }

    // epilogue: + tau*x, store
    #pragma unroll
    for (int i = 0; i < 4; i++) {
        int gn = nbase + ng * 4 + i;
        if (gn >= n_nodes) continue;
        const float* xr = x + (size_t)gn * D + dg * 8;
        float* orow = out + (size_t)gn * D + dg * 8;
        float4 x0 = *(const float4*)(xr);
        float4 x1 = *(const float4*)(xr + 4);
        float r0, r1, r2, r3, r4, r5, r6, r7;
        unpack2(acc[i][0], r0, r1);
        unpack2(acc[i][1], r2, r3);
        unpack2(acc[i][2], r4, r5);
        unpack2(acc[i][3], r6, r7);
        float4 o0 = make_float4(r0 + TAUF * x0.x, r1 + TAUF * x0.y,
                                r2 + TAUF * x0.z, r3 + TAUF * x0.w);
        float4 o1 = make_float4(r4 + TAUF * x1.x, r5 + TAUF * x1.y,
                                r6 + TAUF * x1.z, r7 + TAUF * x1.w);
        *(float4*)(orow)     = o0;
        *(float4*)(orow + 4) = o1;
    }
}

extern "C" void kernel_launch(void* const* d_in, const int* in_sizes, int n_in,
                              void* d_out, int out_size) {
    const float* x  = (const float*)d_in[0];
    const void*  ei = d_in[1];
    const float* w  = (const float*)d_in[2];
    const float* Ws = (const float*)d_in[3];
    const float* Wn = (const float*)d_in[4];

    int n_nodes = in_sizes[0] / D;
    int n_edges = in_sizes[1] / 2;

    float* out_main = (float*)d_out;
    float* out_ei = nullptr;
    float* out_wn = nullptr;
    long long need_full = (long long)n_nodes * D + 3LL * n_edges;
    bool full = ((long long)out_size >= need_full);
    if (full) {
        out_ei = out_main + (size_t)n_nodes * D;
        out_wn = out_ei + (size_t)2 * n_edges;
    }

    const int T = 256;
    int nblk = (n_nodes + T - 1) / T;

    k_init<<<nblk, T>>>((const int*)ei, n_nodes);
    k_edge<<<EBLOCKS, ETHREADS>>>(ei, w, out_ei, n_edges, n_nodes);

    int gw_blocks = ((long long)n_nodes * 32 + T - 1) / T;
    k_gather<<<gw_blocks, T>>>(x, out_wn, n_nodes);

    int gblocks = (n_nodes + TILE_N - 1) / TILE_N;
    k_gemm<<<gblocks, 256>>>(x, Ws, Wn, out_main, n_nodes);
}

// round 17
// speedup vs baseline: 1.1905x; 1.1905x over previous
#include <cuda_runtime.h>
#include <cstdint>
#include <math.h>

#define MAXN 100000
#define MAXE 1600000
#define D 64
#define EPSF 1e-12f
#define SEPS 1e-6f
#define TAUF 0.5f

#define EBLOCKS 592          // 4 blocks/SM x 148 SMs
#define ETHREADS 256
#define NT (EBLOCKS * ETHREADS)
#define MAXK 12

// ---- scratch (device globals: no allocation allowed) ----
__device__ __align__(8)  float2 g_deghist[MAXN];   // {weighted deg, edge count}
__device__ float    g_rho[MAXN];
__device__ int      g_start[MAXN];
__device__ int      g_cursor[MAXN];
__device__ __align__(16) float4 g_pay[MAXE];  // {bitcast col, wh, kappa, bitcast eid}
__device__ __align__(16) float g_agg[MAXN * D];
__device__ unsigned g_maxbits;
__device__ int      g_base;
__device__ int      g_is64;
__device__ int      g_bar1, g_bar2;

__device__ __forceinline__ int get_idx(const void* ei, long long pos) {
    if (g_is64) return (int)((const long long*)ei)[pos];
    return ((const int*)ei)[pos];
}

// ---- 0: zero node scratch + barrier counters + dtype detect (block 0) ----
__global__ void k_init(const int* __restrict__ eib, int n_nodes) {
    if (blockIdx.x == 0) {
        __shared__ int any;
        if (threadIdx.x == 0) any = 0;
        __syncthreads();
        int acc = 0;
        for (int j = threadIdx.x; j < 2048; j += blockDim.x)
            acc |= eib[2 * j + 1];
        if (acc != 0) atomicOr(&any, 1);
        __syncthreads();
        if (threadIdx.x == 0) {
            g_is64 = (any == 0) ? 1 : 0;
            g_maxbits = 0u;
            g_base = 0;
            g_bar1 = 0;
            g_bar2 = 0;
        }
    }
    int i = blockIdx.x * blockDim.x + threadIdx.x;
    if (i < n_nodes)
        g_deghist[i] = make_float2(0.f, 0.f);
}

// software grid barrier: all EBLOCKS blocks are co-resident by construction
__device__ __forceinline__ void grid_barrier(int* bar) {
    __syncthreads();
    if (threadIdx.x == 0) {
        __threadfence();
        atomicAdd(bar, 1);
        while (atomicAdd(bar, 0) < EBLOCKS) { }
    }
    __syncthreads();
}

// ---- 1: persistent fused edge pipeline ----
__global__ void __launch_bounds__(ETHREADS, 4)
k_edge(const void* __restrict__ ei, const float* __restrict__ w,
       float* __restrict__ out_ei, int n_edges, int n_nodes) {
    int gtid = blockIdx.x * ETHREADS + threadIdx.x;

    int er[MAXK], ec[MAXK];
    float kap[MAXK];

    // ---- phase A: convert + out_ei + {deg,count} reduction ----
    #pragma unroll
    for (int k = 0; k < MAXK; k++) {
        int e = gtid + k * NT;
        er[k] = -1;
        if (e < n_edges) {
            int r = get_idx(ei, e);
            int c = get_idx(ei, (long long)n_edges + e);
            er[k] = r; ec[k] = c;
            if (out_ei) {
                out_ei[e] = (float)r;
                out_ei[n_edges + e] = (float)c;
            }
            float* dst = (float*)&g_deghist[r];
            asm volatile("red.global.add.v2.f32 [%0], {%1,%2};"
                         :: "l"(dst), "f"(w[e]), "f"(1.0f) : "memory");
        }
    }

    grid_barrier(&g_bar1);

    // ---- phase B: kappa + max|kappa| + CSR-start rider ----
    float m = 0.f;
    #pragma unroll
    for (int k = 0; k < MAXK; k++) {
        if (er[k] >= 0) {
            float idu = 2.f / fmaxf(g_deghist[er[k]].x, EPSF);
            float idv = 2.f / fmaxf(g_deghist[ec[k]].x, EPSF);
            kap[k] = idu + idv - 2.f;
            m = fmaxf(m, fabsf(kap[k]));
        }
    }
    #pragma unroll
    for (int o = 16; o > 0; o >>= 1)
        m = fmaxf(m, __shfl_xor_sync(0xffffffffu, m, o));
    if ((threadIdx.x & 31) == 0)
        atomicMax(&g_maxbits, __float_as_uint(m));

    {
        __shared__ int sh[ETHREADS];
        __shared__ int sbase;
        int t = threadIdx.x;
        if (blockIdx.x * ETHREADS < (unsigned)n_nodes) {
            int n = blockIdx.x * ETHREADS + t;
            int v = (n < n_nodes) ? (int)g_deghist[n].y : 0;
            sh[t] = v;
            __syncthreads();
            #pragma unroll
            for (int o = 1; o < ETHREADS; o <<= 1) {
                int u = (t >= o) ? sh[t - o] : 0;
                __syncthreads();
                sh[t] += u;
                __syncthreads();
            }
            int incl = sh[t];
            if (t == ETHREADS - 1) sbase = atomicAdd(&g_base, incl);
            __syncthreads();
            if (n < n_nodes) {
                int s = sbase + incl - v;
                g_start[n] = s;
                g_cursor[n] = s;
            }
        }
    }

    grid_barrier(&g_bar2);

    // ---- phase C: whalf + surgery + payload scatter ----
    float dt = 0.5f / (__uint_as_float(g_maxbits) + 1e-6f);
    #pragma unroll
    for (int k = 0; k < MAXK; k++) {
        int e = gtid + k * NT;
        if (er[k] >= 0) {
            float wh = fmaxf(w[e] * (1.f - 0.5f * dt * kap[k]), 0.f);
            if (wh <= SEPS) wh = 0.f;
            int pos = atomicAdd(&g_cursor[er[k]], 1);
            g_pay[pos] = make_float4(__int_as_float(ec[k]), wh, kap[k],
                                     __int_as_float(e));
        }
    }
}

// ---- 2: single-pass gather: stats + accumulate + rho + out_wn ----
__global__ void k_gather(const float* __restrict__ x,
                         float* __restrict__ out_wn, int n_nodes) {
    int node = (blockIdx.x * blockDim.x + threadIdx.x) >> 5;
    if (node >= n_nodes) return;
    int lane = threadIdx.x & 31;
    int sub  = lane & 15;
    int half = lane >> 4;
    int s = g_start[node];
    int deg = (int)g_deghist[node].y;

    float rs = 0.f, cn = 0.f, ks = 0.f;
    float4 acc = make_float4(0.f, 0.f, 0.f, 0.f);
    #pragma unroll 2
    for (int j = half; j < deg; j += 2) {
        float4 pl = g_pay[s + j];
        float wh = pl.y;
        rs += wh;
        if (wh != 0.f) {
            cn += 1.f;
            ks += pl.z;
            int c = __float_as_int(pl.x);
            float4 v = ((const float4*)(x + (size_t)c * D))[sub];
            acc.x += wh * v.x; acc.y += wh * v.y;
            acc.z += wh * v.z; acc.w += wh * v.w;
        }
    }
    rs += __shfl_xor_sync(0xffffffffu, rs, 16);
    cn += __shfl_xor_sync(0xffffffffu, cn, 16);
    ks += __shfl_xor_sync(0xffffffffu, ks, 16);
    acc.x += __shfl_xor_sync(0xffffffffu, acc.x, 16);
    acc.y += __shfl_xor_sync(0xffffffffu, acc.y, 16);
    acc.z += __shfl_xor_sync(0xffffffffu, acc.z, 16);
    acc.w += __shfl_xor_sync(0xffffffffu, acc.w, 16);

    float irs = 1.f / fmaxf(rs, EPSF);
    if (lane == 0) {
        float mk = ks / fmaxf(cn, 1.f);
        g_rho[node] = 1.f / (1.f + expf(-mk));
    }
    if (half == 0) {
        acc.x *= irs; acc.y *= irs; acc.z *= irs; acc.w *= irs;
        *(float4*)(g_agg + (size_t)node * D + sub * 4) = acc;
    }

    if (out_wn) {
        for (int j = lane; j < deg; j += 32) {
            float4 pl = g_pay[s + j];
            out_wn[__float_as_int(pl.w)] = pl.y * irs;
        }
    }
}

// ---- 3: two-pass plain-FFMA GEMM: TILE_N=256, 256 thr, 8x8 tile ----
// out = (rho*x)@Ws^T + agg@Wn^T + tau*x
#define TILE_N 256
__global__ __launch_bounds__(256, 2) void k_gemm(const float* __restrict__ x,
                                                 const float* __restrict__ Ws,
                                                 const float* __restrict__ Wn,
                                                 float* __restrict__ out,
                                                 int n_nodes) {
    extern __shared__ float smem[];
    float* buf = smem;            // [64][256]  operand transposed (64KB)
    float* wT  = buf + D * TILE_N; // [64][64]   weight transposed (16KB)

    int t = threadIdx.x;
    int nbase = blockIdx.x * TILE_N;
    int ng = t >> 3;   // 0..31 -> nodes ng*8 .. +7
    int dg = t & 7;    // 0..7  -> dims  dg*8 .. +7

    float acc[8][8];
    #pragma unroll
    for (int i = 0; i < 8; i++)
        #pragma unroll
        for (int j = 0; j < 8; j++) acc[i][j] = 0.f;

    #pragma unroll
    for (int pass = 0; pass < 2; pass++) {
        const float* W = (pass == 0) ? Ws : Wn;
        for (int i = t; i < D * D; i += 256) {
            int k = i >> 6, d = i & 63;
            wT[k * D + d] = W[d * D + k];
        }
        // stage operand transposed: pass0 = rho*x, pass1 = agg
        for (int i = t; i < TILE_N * (D / 4); i += 256) {
            int n  = i & (TILE_N - 1);
            int k4 = i >> 8;               // 0..15
            int gn = nbase + n;
            float4 v = make_float4(0.f, 0.f, 0.f, 0.f);
            if (gn < n_nodes) {
                if (pass == 0) {
                    v = *(const float4*)(x + (size_t)gn * D + k4 * 4);
                    float rho = g_rho[gn];
                    v.x *= rho; v.y *= rho; v.z *= rho; v.w *= rho;
                } else {
                    v = *(const float4*)(g_agg + (size_t)gn * D + k4 * 4);
                }
            }
            buf[(k4 * 4 + 0) * TILE_N + n] = v.x;
            buf[(k4 * 4 + 1) * TILE_N + n] = v.y;
            buf[(k4 * 4 + 2) * TILE_N + n] = v.z;
            buf[(k4 * 4 + 3) * TILE_N + n] = v.w;
        }
        __syncthreads();

        #pragma unroll 2
        for (int k = 0; k < D; k++) {
            float4 a0 = *(float4*)&buf[k * TILE_N + ng * 8];
            float4 a1 = *(float4*)&buf[k * TILE_N + ng * 8 + 4];
            float4 b0 = *(float4*)&wT[k * D + dg * 8];
            float4 b1 = *(float4*)&wT[k * D + dg * 8 + 4];
            float av[8] = {a0.x, a0.y, a0.z, a0.w, a1.x, a1.y, a1.z, a1.w};
            float bv[8] = {b0.x, b0.y, b0.z, b0.w, b1.x, b1.y, b1.z, b1.w};
            #pragma unroll
            for (int i = 0; i < 8; i++)
                #pragma unroll
                for (int j = 0; j < 8; j++)
                    acc[i][j] += av[i] * bv[j];
        }
        __syncthreads();   // safe to restage
    }

    // epilogue: + tau*x
    #pragma unroll
    for (int i = 0; i < 8; i++) {
        int gn = nbase + ng * 8 + i;
        if (gn >= n_nodes) continue;
        const float* xr = x + (size_t)gn * D + dg * 8;
        float* orow = out + (size_t)gn * D + dg * 8;
        float4 x0 = *(const float4*)(xr);
        float4 x1 = *(const float4*)(xr + 4);
        float4 o0 = make_float4(acc[i][0] + TAUF * x0.x, acc[i][1] + TAUF * x0.y,
                                acc[i][2] + TAUF * x0.z, acc[i][3] + TAUF * x0.w);
        float4 o1 = make_float4(acc[i][4] + TAUF * x1.x, acc[i][5] + TAUF * x1.y,
                                acc[i][6] + TAUF * x1.z, acc[i][7] + TAUF * x1.w);
        *(float4*)(orow)     = o0;
        *(float4*)(orow + 4) = o1;
    }
}

extern "C" void kernel_launch(void* const* d_in, const int* in_sizes, int n_in,
                              void* d_out, int out_size) {
    const float* x  = (const float*)d_in[0];
    const void*  ei = d_in[1];
    const float* w  = (const float*)d_in[2];
    const float* Ws = (const float*)d_in[3];
    const float* Wn = (const float*)d_in[4];

    int n_nodes = in_sizes[0] / D;
    int n_edges = in_sizes[1] / 2;

    float* out_main = (float*)d_out;
    float* out_ei = nullptr;
    float* out_wn = nullptr;
    long long need_full = (long long)n_nodes * D + 3LL * n_edges;
    bool full = ((long long)out_size >= need_full);
    if (full) {
        out_ei = out_main + (size_t)n_nodes * D;
        out_wn = out_ei + (size_t)2 * n_edges;
    }

    const int T = 256;
    int nblk = (n_nodes + T - 1) / T;

    k_init<<<nblk, T>>>((const int*)ei, n_nodes);
    k_edge<<<EBLOCKS, ETHREADS>>>(ei, w, out_ei, n_edges, n_nodes);

    int gw_blocks = ((long long)n_nodes * 32 + T - 1) / T;
    k_gather<<<gw_blocks, T>>>(x, out_wn, n_nodes);

    int smem_bytes = (D * TILE_N + D * D) * (int)sizeof(float); // 80KB
    cudaFuncSetAttribute(k_gemm, cudaFuncAttributeMaxDynamicSharedMemorySize, smem_bytes);
    int gblocks = (n_nodes + TILE_N - 1) / TILE_N;
    k_gemm<<<gblocks, 256, smem_bytes>>>(x, Ws, Wn, out_main, n_nodes);
}